// round 13
// baseline (speedup 1.0000x reference)
#include <cuda_runtime.h>
#include <cuda_bf16.h>
#include <cuda_fp16.h>
#include <cstdint>

#define B_ROWS 8192
#define DFEAT  512
#define KOUT   1024

// Scratch (__device__ globals; no dynamic allocation allowed)
__device__ __align__(16) unsigned char g_xf8[B_ROWS * DFEAT];   // 4 MB e4m3
__device__ __align__(16) unsigned char g_wf8[KOUT * DFEAT];     // 0.5 MB e4m3
__device__ float g_xsq[B_ROWS];
__device__ float g_wsq[KOUT];
__device__ float g_rowsum[B_ROWS];
__device__ int   g_cnt[64];

// ---------------------------------------------------------------------------
// Kernel 1: convert x,w to e4m3 + fp32 row squared norms. 4 rows per warp.
// Also zeroes g_rowsum / g_cnt for the fused-norm reduction (graph-safe).
// ---------------------------------------------------------------------------
__device__ __forceinline__ uint16_t pack_e4m3x2(float hi, float lo) {
    uint16_t h;
    asm("cvt.rn.satfinite.e4m3x2.f32 %0, %1, %2;" : "=h"(h) : "f"(hi), "f"(lo));
    return h;
}

__global__ void prep_kernel(const float* __restrict__ x, const float* __restrict__ w) {
    int gt = blockIdx.x * blockDim.x + threadIdx.x;
    if (gt < B_ROWS) g_rowsum[gt] = 0.0f;
    if (gt < 64)     g_cnt[gt] = 0;

    int gw   = gt >> 5;
    int lane = threadIdx.x & 31;
    int r0 = gw * 4;

    const float* src[4];
    unsigned char* dst[4];
    float* sqp[4];
    int sqi[4];
#pragma unroll
    for (int j = 0; j < 4; j++) {
        int r = r0 + j;
        if (r < B_ROWS) {
            src[j] = x + (size_t)r * DFEAT;
            dst[j] = g_xf8 + (size_t)r * DFEAT;
            sqp[j] = g_xsq; sqi[j] = r;
        } else {
            int rr = r - B_ROWS;
            src[j] = w + (size_t)rr * DFEAT;
            dst[j] = g_wf8 + (size_t)rr * DFEAT;
            sqp[j] = g_wsq; sqi[j] = rr;
        }
    }

    float4 v[4][4];
#pragma unroll
    for (int j = 0; j < 4; j++)
#pragma unroll
        for (int i = 0; i < 4; i++)
            v[j][i] = *reinterpret_cast<const float4*>(src[j] + i * 128 + lane * 4);

#pragma unroll
    for (int j = 0; j < 4; j++) {
        float s = 0.0f;
#pragma unroll
        for (int i = 0; i < 4; i++) {
            float4 q = v[j][i];
            s += q.x * q.x + q.y * q.y + q.z * q.z + q.w * q.w;
            uint32_t pk = ((uint32_t)pack_e4m3x2(q.w, q.z) << 16)
                        |  (uint32_t)pack_e4m3x2(q.y, q.x);
            *reinterpret_cast<uint32_t*>(dst[j] + i * 128 + lane * 4) = pk;
        }
#pragma unroll
        for (int off = 16; off >= 1; off >>= 1)
            s += __shfl_xor_sync(0xFFFFFFFFu, s, off);
        if (lane == 0) sqp[j][sqi[j]] = s;
    }
}

// ---------------------------------------------------------------------------
// Kernel 2: e4m3 mma.sync GEMM + fused normalization with LATENCY-HIDDEN
// cross-CTA reduction. Persistent 256 CTAs (one wave, 2/SM), 2 tiles each.
// tile0: compute -> contribute sums -> park q_un (f16, smem) ->
// tile1: compute -> contribute sums -> settle tile0 (counter already full,
// zero spin) -> settle tile1 (single exposed spin ~ skew).
// ---------------------------------------------------------------------------
#define TILE_BYTES (128 * 144)            // one A or B stage tile, 144B pitch
#define STAGE_BYTES (2 * TILE_BYTES)      // 36864
#define NSTAGE 2
#define OFF_SQ   (NSTAGE * STAGE_BYTES)   // 73728: sXsq[128], sWsq[128]
#define OFF_SUM  (OFF_SQ + 1024)          // 74752: ssum[128][2]
#define OFF_PARK (OFF_SUM + 1024)         // 75776: 8 warps * 1024 words
#define GEMM_SMEM (OFF_PARK + 32768)      // 108544 -> 2 CTAs/SM

__device__ __forceinline__ void ldmatrix_x4(uint32_t& r0, uint32_t& r1,
                                            uint32_t& r2, uint32_t& r3,
                                            uint32_t saddr) {
    asm volatile("ldmatrix.sync.aligned.m8n8.x4.shared.b16 {%0,%1,%2,%3}, [%4];"
                 : "=r"(r0), "=r"(r1), "=r"(r2), "=r"(r3) : "r"(saddr));
}

__device__ __forceinline__ void mma_fp8(float* d, const uint32_t* a,
                                        uint32_t b0, uint32_t b1) {
    asm volatile(
        "mma.sync.aligned.m16n8k32.row.col.f32.e4m3.e4m3.f32 "
        "{%0,%1,%2,%3}, {%4,%5,%6,%7}, {%8,%9}, {%0,%1,%2,%3};"
        : "+f"(d[0]), "+f"(d[1]), "+f"(d[2]), "+f"(d[3])
        : "r"(a[0]), "r"(a[1]), "r"(a[2]), "r"(a[3]), "r"(b0), "r"(b1));
}

__device__ __forceinline__ void cp16(uint32_t s, const void* g) {
    asm volatile("cp.async.cg.shared.global [%0], [%1], 16;" :: "r"(s), "l"(g));
}

__device__ __forceinline__ void load_stage(uint32_t sbase, int stage, int kc,
                                           int m0, int n0, int tid) {
    const char* gA = (const char*)g_xf8 + (size_t)m0 * 512 + (size_t)kc * 128;
    const char* gB = (const char*)g_wf8 + (size_t)n0 * 512 + (size_t)kc * 128;
    uint32_t aB = sbase + stage * STAGE_BYTES;
    uint32_t bB = aB + TILE_BYTES;
#pragma unroll
    for (int i = 0; i < 4; i++) {
        int idx = tid + i * 256;
        int row = idx >> 3;
        int cb  = (idx & 7) << 4;
        cp16(aB + row * 144 + cb, gA + (size_t)row * 512 + cb);
        cp16(bB + row * 144 + cb, gB + (size_t)row * 512 + cb);
    }
}

__device__ __forceinline__ uint32_t f16x2_pack(float a, float b) {
    __half2 h = __floats2half2_rn(a, b);
    return *reinterpret_cast<uint32_t*>(&h);
}

__global__ __launch_bounds__(256, 2) void gemm_kernel(float* __restrict__ out) {
    extern __shared__ __align__(16) char smem[];
    uint32_t sbase;
    asm("{ .reg .u64 t; cvta.to.shared.u64 t, %1; cvt.u32.u64 %0, t; }"
        : "=r"(sbase) : "l"(smem));

    const int tid  = threadIdx.x;
    const int lane = tid & 31;
    const int warp = tid >> 5;
    const int wm = warp & 3;
    const int wn = warp >> 2;

    float* sXsq = reinterpret_cast<float*>(smem + OFF_SQ);
    float* sWsq = sXsq + 128;
    float* ssum = reinterpret_cast<float*>(smem + OFF_SUM);
    uint32_t* park = reinterpret_cast<uint32_t*>(smem + OFF_PARK) + warp * 1024 + lane;

    const int a_row = (lane & 15);
    const int a_cb  = (lane >> 4) << 4;
    const int b_r   = lane & 7;
    const int b_sel = lane >> 3;
    const int b_nof = ((b_sel >> 1) << 3) + b_r;
    const int b_kb  = (b_sel & 1) << 4;
    const int qt = lane >> 2;
    const int qr = lane & 3;

    const int grp0 = (int)blockIdx.x >> 3;
    const int n0   = ((int)blockIdx.x & 7) * 128;
    const int m0a  = grp0 * 128;
    const int m0b  = m0a + 4096;       // tile1 = grp0 + 32

    float acc[2][8][4];

#pragma unroll 1
    for (int t = 0; t < 2; t++) {
        const int m0 = t ? m0b : m0a;
        __syncthreads();
        if (tid < 128) {
            sXsq[tid] = g_xsq[m0 + tid];
            sWsq[tid] = g_wsq[n0 + tid];
        }
#pragma unroll
        for (int mi = 0; mi < 2; mi++)
#pragma unroll
            for (int ni = 0; ni < 8; ni++)
#pragma unroll
                for (int e = 0; e < 4; e++) acc[mi][ni][e] = 0.0f;

        load_stage(sbase, 0, 0, m0, n0, tid);
        asm volatile("cp.async.commit_group;" ::: "memory");
        load_stage(sbase, 1, 1, m0, n0, tid);
        asm volatile("cp.async.commit_group;" ::: "memory");

#pragma unroll 1
        for (int kc = 0; kc < 4; kc++) {
            if (kc < 3) asm volatile("cp.async.wait_group 1;" ::: "memory");
            else        asm volatile("cp.async.wait_group 0;" ::: "memory");
            __syncthreads();

            uint32_t aBase = sbase + (kc & 1) * STAGE_BYTES;
            uint32_t bBase = aBase + TILE_BYTES;

#pragma unroll
            for (int ks = 0; ks < 128; ks += 32) {
                uint32_t af[2][4];
#pragma unroll
                for (int mi = 0; mi < 2; mi++) {
                    int r = wm * 32 + mi * 16 + a_row;
                    ldmatrix_x4(af[mi][0], af[mi][1], af[mi][2], af[mi][3],
                                aBase + r * 144 + ks + a_cb);
                }
                uint32_t bfr[4][4];
#pragma unroll
                for (int j = 0; j < 4; j++) {
                    int n = wn * 64 + j * 16 + b_nof;
                    ldmatrix_x4(bfr[j][0], bfr[j][1], bfr[j][2], bfr[j][3],
                                bBase + n * 144 + ks + b_kb);
                }
#pragma unroll
                for (int mi = 0; mi < 2; mi++)
#pragma unroll
                    for (int ni = 0; ni < 8; ni++) {
                        int j = ni >> 1, h = (ni & 1) * 2;
                        mma_fp8(acc[mi][ni], af[mi], bfr[j][h], bfr[j][h + 1]);
                    }
            }
            if (kc + 2 < 4) {
                __syncthreads();   // all warps done reading stage kc&1
                load_stage(sbase, kc & 1, kc + 2, m0, n0, tid);
                asm volatile("cp.async.commit_group;" ::: "memory");
            }
        }

        // q_un in regs + row-sum contribution for this tile's group
        float s[2][2] = {{0.0f, 0.0f}, {0.0f, 0.0f}};
#pragma unroll
        for (int mi = 0; mi < 2; mi++) {
            int lr = wm * 32 + mi * 16 + qt;
            float xs0 = sXsq[lr];
            float xs1 = sXsq[lr + 8];
#pragma unroll
            for (int ni = 0; ni < 8; ni++) {
                int nl = wn * 64 + ni * 8 + qr * 2;
                float w0 = sWsq[nl];
                float w1 = sWsq[nl + 1];
                float* d = acc[mi][ni];
                float q00 = 1.0f / (1.0f + fmaxf(xs0 + w0 - 2.0f * d[0], 0.0f));
                float q01 = 1.0f / (1.0f + fmaxf(xs0 + w1 - 2.0f * d[1], 0.0f));
                float q10 = 1.0f / (1.0f + fmaxf(xs1 + w0 - 2.0f * d[2], 0.0f));
                float q11 = 1.0f / (1.0f + fmaxf(xs1 + w1 - 2.0f * d[3], 0.0f));
                d[0] = q00; d[1] = q01; d[2] = q10; d[3] = q11;
                s[mi][0] += q00 + q01;
                s[mi][1] += q10 + q11;
            }
        }
#pragma unroll
        for (int mi = 0; mi < 2; mi++)
#pragma unroll
            for (int h = 0; h < 2; h++) {
                s[mi][h] += __shfl_xor_sync(0xFFFFFFFFu, s[mi][h], 1);
                s[mi][h] += __shfl_xor_sync(0xFFFFFFFFu, s[mi][h], 2);
            }
        if (qr == 0) {
#pragma unroll
            for (int mi = 0; mi < 2; mi++)
#pragma unroll
                for (int h = 0; h < 2; h++)
                    ssum[(wm * 32 + mi * 16 + h * 8 + qt) * 2 + wn] = s[mi][h];
        }
        __syncthreads();
        if (tid < 128) {
            atomicAdd(&g_rowsum[m0 + tid], ssum[2 * tid] + ssum[2 * tid + 1]);
            __threadfence();
        }
        __syncthreads();
        if (tid == 0) atomicAdd(&g_cnt[grp0 + t * 32], 1);

        if (t == 0) {
            // park tile0's q_un as f16x2 (bank-interleaved: word k at lane stride)
#pragma unroll
            for (int mi = 0; mi < 2; mi++)
#pragma unroll
                for (int ni = 0; ni < 8; ni++) {
                    const float* d = acc[mi][ni];
                    park[(mi * 16 + ni * 2 + 0) * 32] = f16x2_pack(d[0], d[1]);
                    park[(mi * 16 + ni * 2 + 1) * 32] = f16x2_pack(d[2], d[3]);
                }
        }
    }

    // ---- settle tile0 (counter filled during tile1 compute: ~zero spin) ----
    if (tid == 0) {
        volatile int* c = &g_cnt[grp0];
        while (*c < 8) { }
    }
    __syncthreads();
#pragma unroll
    for (int mi = 0; mi < 2; mi++) {
        int lr = wm * 32 + mi * 16 + qt;
        float inv0 = 1.0f / __ldcg(&g_rowsum[m0a + lr]);
        float inv1 = 1.0f / __ldcg(&g_rowsum[m0a + lr + 8]);
        int gr0 = (m0a + lr) * KOUT;
        int gr1 = gr0 + 8 * KOUT;
#pragma unroll
        for (int ni = 0; ni < 8; ni++) {
            int nl = wn * 64 + ni * 8 + qr * 2;
            __half2 h0, h1;
            uint32_t u0 = park[(mi * 16 + ni * 2 + 0) * 32];
            uint32_t u1 = park[(mi * 16 + ni * 2 + 1) * 32];
            h0 = *reinterpret_cast<__half2*>(&u0);
            h1 = *reinterpret_cast<__half2*>(&u1);
            float2 f0 = __half22float2(h0);
            float2 f1 = __half22float2(h1);
            *reinterpret_cast<float2*>(&out[gr0 + n0 + nl]) =
                make_float2(f0.x * inv0, f0.y * inv0);
            *reinterpret_cast<float2*>(&out[gr1 + n0 + nl]) =
                make_float2(f1.x * inv1, f1.y * inv1);
        }
    }

    // ---- settle tile1 (single exposed spin ~ CTA skew) ----
    if (tid == 0) {
        volatile int* c = &g_cnt[grp0 + 32];
        while (*c < 8) { }
    }
    __syncthreads();
#pragma unroll
    for (int mi = 0; mi < 2; mi++) {
        int lr = wm * 32 + mi * 16 + qt;
        float inv0 = 1.0f / __ldcg(&g_rowsum[m0b + lr]);
        float inv1 = 1.0f / __ldcg(&g_rowsum[m0b + lr + 8]);
        int gr0 = (m0b + lr) * KOUT;
        int gr1 = gr0 + 8 * KOUT;
#pragma unroll
        for (int ni = 0; ni < 8; ni++) {
            int nl = wn * 64 + ni * 8 + qr * 2;
            const float* d = acc[mi][ni];
            *reinterpret_cast<float2*>(&out[gr0 + n0 + nl]) =
                make_float2(d[0] * inv0, d[1] * inv0);
            *reinterpret_cast<float2*>(&out[gr1 + n0 + nl]) =
                make_float2(d[2] * inv1, d[3] * inv1);
        }
    }
}

// ---------------------------------------------------------------------------
extern "C" void kernel_launch(void* const* d_in, const int* in_sizes, int n_in,
                              void* d_out, int out_size) {
    const float* x = (const float*)d_in[0];   // [8192, 512] f32
    const float* w = (const float*)d_in[1];   // [1024, 512] f32
    float* out = (float*)d_out;               // [8192, 1024] f32

    cudaFuncSetAttribute(gemm_kernel, cudaFuncAttributeMaxDynamicSharedMemorySize,
                         GEMM_SMEM);

    prep_kernel<<<288, 256>>>(x, w);
    gemm_kernel<<<256, 256, GEMM_SMEM>>>(out);
}

// round 14
// speedup vs baseline: 1.1957x; 1.1957x over previous
#include <cuda_runtime.h>
#include <cuda_bf16.h>
#include <cuda_fp16.h>
#include <cstdint>

#define B_ROWS 8192
#define DFEAT  512
#define KOUT   1024

// Scratch (__device__ globals; no dynamic allocation allowed)
__device__ __align__(16) unsigned char g_xf8[B_ROWS * DFEAT];   // 4 MB e4m3
__device__ __align__(16) unsigned char g_wf8[KOUT * DFEAT];     // 0.5 MB e4m3
__device__ float g_xsq[B_ROWS];
__device__ float g_wsq[KOUT];
__device__ float g_rowsum[B_ROWS];
__device__ int   g_cnt[64];

// ---------------------------------------------------------------------------
// Kernel 1: convert x,w to e4m3 + fp32 row squared norms. 4 rows per warp.
// Also zeroes g_rowsum / g_cnt for the fused-norm reduction (graph-safe).
// ---------------------------------------------------------------------------
__device__ __forceinline__ uint16_t pack_e4m3x2(float hi, float lo) {
    uint16_t h;
    asm("cvt.rn.satfinite.e4m3x2.f32 %0, %1, %2;" : "=h"(h) : "f"(hi), "f"(lo));
    return h;
}

__global__ void prep_kernel(const float* __restrict__ x, const float* __restrict__ w) {
    int gt = blockIdx.x * blockDim.x + threadIdx.x;
    if (gt < B_ROWS) g_rowsum[gt] = 0.0f;
    if (gt < 64)     g_cnt[gt] = 0;

    int gw   = gt >> 5;
    int lane = threadIdx.x & 31;
    int r0 = gw * 4;

    const float* src[4];
    unsigned char* dst[4];
    float* sqp[4];
    int sqi[4];
#pragma unroll
    for (int j = 0; j < 4; j++) {
        int r = r0 + j;
        if (r < B_ROWS) {
            src[j] = x + (size_t)r * DFEAT;
            dst[j] = g_xf8 + (size_t)r * DFEAT;
            sqp[j] = g_xsq; sqi[j] = r;
        } else {
            int rr = r - B_ROWS;
            src[j] = w + (size_t)rr * DFEAT;
            dst[j] = g_wf8 + (size_t)rr * DFEAT;
            sqp[j] = g_wsq; sqi[j] = rr;
        }
    }

    float4 v[4][4];
#pragma unroll
    for (int j = 0; j < 4; j++)
#pragma unroll
        for (int i = 0; i < 4; i++)
            v[j][i] = *reinterpret_cast<const float4*>(src[j] + i * 128 + lane * 4);

#pragma unroll
    for (int j = 0; j < 4; j++) {
        float s = 0.0f;
#pragma unroll
        for (int i = 0; i < 4; i++) {
            float4 q = v[j][i];
            s += q.x * q.x + q.y * q.y + q.z * q.z + q.w * q.w;
            uint32_t pk = ((uint32_t)pack_e4m3x2(q.w, q.z) << 16)
                        |  (uint32_t)pack_e4m3x2(q.y, q.x);
            *reinterpret_cast<uint32_t*>(dst[j] + i * 128 + lane * 4) = pk;
        }
#pragma unroll
        for (int off = 16; off >= 1; off >>= 1)
            s += __shfl_xor_sync(0xFFFFFFFFu, s, off);
        if (lane == 0) sqp[j][sqi[j]] = s;
    }
}

// ---------------------------------------------------------------------------
// Kernel 2: e4m3 mma.sync (m16n8k32, f16 accumulator = 2x rate on fallback
// fp8 path) GEMM with fused normalization (R12 structure).
// Persistent: 256 CTAs (one wave at 2 CTAs/SM), 2 tiles each.
// ---------------------------------------------------------------------------
#define TILE_BYTES (128 * 144)
#define STAGE_BYTES (2 * TILE_BYTES)
#define NSTAGE 3
#define OFF_SQ  (NSTAGE * STAGE_BYTES)    // 110592
#define OFF_SUM (OFF_SQ + 1024)           // 111616
#define GEMM_SMEM (OFF_SUM + 1024)        // 112640 -> 2 CTAs/SM

__device__ __forceinline__ void ldmatrix_x4(uint32_t& r0, uint32_t& r1,
                                            uint32_t& r2, uint32_t& r3,
                                            uint32_t saddr) {
    asm volatile("ldmatrix.sync.aligned.m8n8.x4.shared.b16 {%0,%1,%2,%3}, [%4];"
                 : "=r"(r0), "=r"(r1), "=r"(r2), "=r"(r3) : "r"(saddr));
}

// fp8 mma with f16 accumulator: D(f16x2 x2) = A(e4m3) * B(e4m3) + D
__device__ __forceinline__ void mma_fp8_h(uint32_t* d, const uint32_t* a,
                                          uint32_t b0, uint32_t b1) {
    asm volatile(
        "mma.sync.aligned.m16n8k32.row.col.f16.e4m3.e4m3.f16 "
        "{%0,%1}, {%2,%3,%4,%5}, {%6,%7}, {%0,%1};"
        : "+r"(d[0]), "+r"(d[1])
        : "r"(a[0]), "r"(a[1]), "r"(a[2]), "r"(a[3]), "r"(b0), "r"(b1));
}

__device__ __forceinline__ void cp16(uint32_t s, const void* g) {
    asm volatile("cp.async.cg.shared.global [%0], [%1], 16;" :: "r"(s), "l"(g));
}

__device__ __forceinline__ void load_stage(uint32_t sbase, int stage, int kc,
                                           int m0, int n0, int tid) {
    const char* gA = (const char*)g_xf8 + (size_t)m0 * 512 + (size_t)kc * 128;
    const char* gB = (const char*)g_wf8 + (size_t)n0 * 512 + (size_t)kc * 128;
    uint32_t aB = sbase + stage * STAGE_BYTES;
    uint32_t bB = aB + TILE_BYTES;
#pragma unroll
    for (int i = 0; i < 4; i++) {
        int idx = tid + i * 256;
        int row = idx >> 3;
        int cb  = (idx & 7) << 4;
        cp16(aB + row * 144 + cb, gA + (size_t)row * 512 + cb);
        cp16(bB + row * 144 + cb, gB + (size_t)row * 512 + cb);
    }
}

__global__ __launch_bounds__(256, 2) void gemm_kernel(float* __restrict__ out) {
    extern __shared__ __align__(16) char smem[];
    uint32_t sbase;
    asm("{ .reg .u64 t; cvta.to.shared.u64 t, %1; cvt.u32.u64 %0, t; }"
        : "=r"(sbase) : "l"(smem));

    const int tid  = threadIdx.x;
    const int lane = tid & 31;
    const int warp = tid >> 5;
    const int wm = warp & 3;
    const int wn = warp >> 2;

    float* sXsq = reinterpret_cast<float*>(smem + OFF_SQ);
    float* sWsq = sXsq + 128;
    float* ssum = reinterpret_cast<float*>(smem + OFF_SUM);

    const int a_row = (lane & 15);
    const int a_cb  = (lane >> 4) << 4;
    const int b_r   = lane & 7;
    const int b_sel = lane >> 3;
    const int b_nof = ((b_sel >> 1) << 3) + b_r;
    const int b_kb  = (b_sel & 1) << 4;
    const int qt = lane >> 2;
    const int qr = lane & 3;

#pragma unroll 1
    for (int t = 0; t < 2; t++) {
        const int tile = (int)blockIdx.x + t * 256;
        const int ygrp = tile >> 3;
        const int m0 = ygrp * 128;
        const int n0 = (tile & 7) * 128;

        __syncthreads();
        if (tid < 128) {
            sXsq[tid] = g_xsq[m0 + tid];
            sWsq[tid] = g_wsq[n0 + tid];
        }

        uint32_t acc[2][8][2];   // f16x2 accumulators
#pragma unroll
        for (int mi = 0; mi < 2; mi++)
#pragma unroll
            for (int ni = 0; ni < 8; ni++) {
                acc[mi][ni][0] = 0u;
                acc[mi][ni][1] = 0u;
            }

        load_stage(sbase, 0, 0, m0, n0, tid);
        asm volatile("cp.async.commit_group;" ::: "memory");
        load_stage(sbase, 1, 1, m0, n0, tid);
        asm volatile("cp.async.commit_group;" ::: "memory");

#pragma unroll 1
        for (int kc = 0; kc < 4; kc++) {
            const int st = kc % NSTAGE;
            if (kc < 3) asm volatile("cp.async.wait_group 1;" ::: "memory");
            else        asm volatile("cp.async.wait_group 0;" ::: "memory");
            __syncthreads();

            if (kc + 2 < 4) {
                load_stage(sbase, (kc + 2) % NSTAGE, kc + 2, m0, n0, tid);
                asm volatile("cp.async.commit_group;" ::: "memory");
            }

            uint32_t aBase = sbase + st * STAGE_BYTES;
            uint32_t bBase = aBase + TILE_BYTES;

#pragma unroll
            for (int ks = 0; ks < 128; ks += 32) {
                uint32_t af[2][4];
#pragma unroll
                for (int mi = 0; mi < 2; mi++) {
                    int r = wm * 32 + mi * 16 + a_row;
                    ldmatrix_x4(af[mi][0], af[mi][1], af[mi][2], af[mi][3],
                                aBase + r * 144 + ks + a_cb);
                }
                uint32_t bfr[4][4];
#pragma unroll
                for (int j = 0; j < 4; j++) {
                    int n = wn * 64 + j * 16 + b_nof;
                    ldmatrix_x4(bfr[j][0], bfr[j][1], bfr[j][2], bfr[j][3],
                                bBase + n * 144 + ks + b_kb);
                }
#pragma unroll
                for (int mi = 0; mi < 2; mi++)
#pragma unroll
                    for (int ni = 0; ni < 8; ni++) {
                        int j = ni >> 1, h = (ni & 1) * 2;
                        mma_fp8_h(acc[mi][ni], af[mi], bfr[j][h], bfr[j][h + 1]);
                    }
            }
        }

        // ---- Fused epilogue: unpack f16 acc -> q_un fp32 + row-sum reduce ----
        float q[2][8][4];
        float s[2][2] = {{0.0f, 0.0f}, {0.0f, 0.0f}};
#pragma unroll
        for (int mi = 0; mi < 2; mi++) {
            int lr = wm * 32 + mi * 16 + qt;
            float xs0 = sXsq[lr];
            float xs1 = sXsq[lr + 8];
#pragma unroll
            for (int ni = 0; ni < 8; ni++) {
                int nl = wn * 64 + ni * 8 + qr * 2;
                float w0 = sWsq[nl];
                float w1 = sWsq[nl + 1];
                float2 f0 = __half22float2(
                    *reinterpret_cast<__half2*>(&acc[mi][ni][0]));
                float2 f1 = __half22float2(
                    *reinterpret_cast<__half2*>(&acc[mi][ni][1]));
                float q00 = 1.0f / (1.0f + fmaxf(xs0 + w0 - 2.0f * f0.x, 0.0f));
                float q01 = 1.0f / (1.0f + fmaxf(xs0 + w1 - 2.0f * f0.y, 0.0f));
                float q10 = 1.0f / (1.0f + fmaxf(xs1 + w0 - 2.0f * f1.x, 0.0f));
                float q11 = 1.0f / (1.0f + fmaxf(xs1 + w1 - 2.0f * f1.y, 0.0f));
                q[mi][ni][0] = q00; q[mi][ni][1] = q01;
                q[mi][ni][2] = q10; q[mi][ni][3] = q11;
                s[mi][0] += q00 + q01;
                s[mi][1] += q10 + q11;
            }
        }
#pragma unroll
        for (int mi = 0; mi < 2; mi++)
#pragma unroll
            for (int h = 0; h < 2; h++) {
                s[mi][h] += __shfl_xor_sync(0xFFFFFFFFu, s[mi][h], 1);
                s[mi][h] += __shfl_xor_sync(0xFFFFFFFFu, s[mi][h], 2);
            }
        if (qr == 0) {
#pragma unroll
            for (int mi = 0; mi < 2; mi++)
#pragma unroll
                for (int h = 0; h < 2; h++)
                    ssum[(wm * 32 + mi * 16 + h * 8 + qt) * 2 + wn] = s[mi][h];
        }
        __syncthreads();
        if (tid < 128)
            atomicAdd(&g_rowsum[m0 + tid], ssum[2 * tid] + ssum[2 * tid + 1]);
        __threadfence();
        __syncthreads();
        if (tid == 0) {
            atomicAdd(&g_cnt[ygrp], 1);
            while (atomicAdd(&g_cnt[ygrp], 0) < 8) { }
        }
        __syncthreads();

        float inv[2][2];
#pragma unroll
        for (int mi = 0; mi < 2; mi++)
#pragma unroll
            for (int h = 0; h < 2; h++)
                inv[mi][h] = 1.0f /
                    __ldcg(&g_rowsum[m0 + wm * 32 + mi * 16 + h * 8 + qt]);

#pragma unroll
        for (int mi = 0; mi < 2; mi++) {
            int lr = wm * 32 + mi * 16 + qt;
            int gr0 = (m0 + lr) * KOUT;
            int gr1 = gr0 + 8 * KOUT;
#pragma unroll
            for (int ni = 0; ni < 8; ni++) {
                int nl = wn * 64 + ni * 8 + qr * 2;
                const float* d = q[mi][ni];
                *reinterpret_cast<float2*>(&out[gr0 + n0 + nl]) =
                    make_float2(d[0] * inv[mi][0], d[1] * inv[mi][0]);
                *reinterpret_cast<float2*>(&out[gr1 + n0 + nl]) =
                    make_float2(d[2] * inv[mi][1], d[3] * inv[mi][1]);
            }
        }
    }
}

// ---------------------------------------------------------------------------
extern "C" void kernel_launch(void* const* d_in, const int* in_sizes, int n_in,
                              void* d_out, int out_size) {
    const float* x = (const float*)d_in[0];   // [8192, 512] f32
    const float* w = (const float*)d_in[1];   // [1024, 512] f32
    float* out = (float*)d_out;               // [8192, 1024] f32

    cudaFuncSetAttribute(gemm_kernel, cudaFuncAttributeMaxDynamicSharedMemorySize,
                         GEMM_SMEM);

    prep_kernel<<<288, 256>>>(x, w);
    gemm_kernel<<<256, 256, GEMM_SMEM>>>(out);
}